// round 16
// baseline (speedup 1.0000x reference)
#include <cuda_runtime.h>
#include <cuda_bf16.h>
#include <math.h>
#include <stdint.h>

// Problem constants (reference: N=1024, L=30, G=10000, NB=64)
#define LDIM    30
#define GPB     128          // genes per block (= THREADS, 1 gene/thread)
#define THREADS 128
#define CSTRIDE 31           // csm row stride (odd -> conflict-free lane reads)
#define MAXCC   128          // cells per chunk (zsT capacity)
#define GRP     16           // cells per inner group (8 f32x2 accumulators)
#define NMAX    1024

typedef unsigned long long u64;

#define FFMA2(d, a, b, c) \
    asm("fma.rn.f32x2 %0, %1, %2, %3;" : "=l"(d) : "l"(a), "l"(b), "l"(c))
#define PACK2(d, x) \
    asm("mov.b64 %0, {%1, %2};" : "=l"(d) : "f"(x), "f"(x))
#define UNPACK2(lo, hi, v) \
    asm("mov.b64 {%0, %1}, %2;" : "=f"(lo), "=f"(hi) : "l"(v))

__device__ __forceinline__ float softplus_fast(float x) {
    // max(x,0) + log1p(exp(-|x|)); fast intrinsics (rel err ~1e-6 << 1e-3 budget)
    return fmaxf(x, 0.0f) + __logf(1.0f + __expf(-fabsf(x)));
}

__device__ __forceinline__ void cp_async16(unsigned int saddr, const void* gptr) {
    asm volatile("cp.async.cg.shared.global [%0], [%1], 16;\n" :: "r"(saddr), "l"(gptr));
}
__device__ __forceinline__ void cp_commit() { asm volatile("cp.async.commit_group;\n" ::: "memory"); }
__device__ __forceinline__ void cp_wait0()  { asm volatile("cp.async.wait_group 0;\n" ::: "memory"); }

// ---------------------------------------------------------------------------
// grid = (ceil(G/GPB), NB + 1), block = 128.
//  y < NB : decoder, batch y, 128-gene tile. Structure:
//    - A tile cp.async'd into zsT region (aliased), combined coeffs
//      c[g][l] = W[l,g] + A[b,g,l] written to csm (stride 31, scalar).
//    - z staged TRANSPOSED in zsT[l][cell] (cell-pairs -> f32x2 lanes).
//    - l-outer mainloop: per l: 1 LDS.32 (c) + pack + 4 LDS.128 (16 cells' z)
//      + 8 FFMA2  => 0.875 issue slots per MAC, regs stay low (~accs only).
//  y == NB: inverse_dispersion = exp(px_r)
// ---------------------------------------------------------------------------
__global__ __launch_bounds__(THREADS, 6) void fused_decoder_kernel(
    const float* __restrict__ z,      // [N, L]
    const int*   __restrict__ bc,     // [N]
    const float* __restrict__ sf,     // [N, 1]
    const float* __restrict__ W,      // [L, G]
    const float* __restrict__ A,      // [NB, G, L]
    const float* __restrict__ bemb,   // [NB, G]
    const float* __restrict__ px_r,   // [G]
    float* __restrict__ out,          // [N, G] ++ [G]
    int N, int G, int NB)
{
    // ---- exp(px_r) slice ----
    if (blockIdx.y == (unsigned)NB) {
        float* od = out + (size_t)N * G;
        for (int g = blockIdx.x * THREADS + threadIdx.x; g < G; g += gridDim.x * THREADS)
            od[g] = __expf(px_r[g]);
        return;
    }

    __shared__ float csm[GPB * CSTRIDE];    // 15.9 KB combined coeffs (scalar)
    __shared__ float zsT[LDIM * MAXCC];     // 15.4 KB transposed z chunk; ALSO the
                                            //         A staging buffer (aliased)
    __shared__ int   cells[NMAX + GRP];     //  4.2 KB cell list (padded to GRP mult)
    __shared__ float sfs[MAXCC];
    __shared__ int   scount;

    const int tid   = threadIdx.x;
    const int b     = blockIdx.y;
    const int gbase = blockIdx.x * GPB;
    const int nst   = min(GPB, G - gbase);

    // ---- 1. kick off A tile load into zsT (alias), hide behind compaction ----
    {
        const float*  srcf = A + ((size_t)b * G + gbase) * LDIM;
        unsigned int  dst  = (unsigned int)__cvta_generic_to_shared(&zsT[0]);
        const int w4 = (nst * LDIM) >> 2;            // nst*30 divisible by 4 here
        const float4* src4 = (const float4*)srcf;
        for (int i = tid; i < w4; i += THREADS) cp_async16(dst + i * 16, src4 + i);
    }
    cp_commit();

    // ---- 2. compact this batch's cell list (bc: 4 KB, L2-hot) ----
    if (tid == 0) scount = 0;
    __syncthreads();
    for (int n = tid; n < N; n += THREADS) {
        if (bc[n] == b) {
            int p = atomicAdd(&scount, 1);
            cells[p] = n;
        }
    }
    cp_wait0();
    __syncthreads();                       // cells/scount + A(zsT) visible
    const int ncell = scount;
    if (ncell == 0) return;                // uniform across block
    const int ncp = (ncell + GRP - 1) & ~(GRP - 1);
    if (tid < ncp - ncell) cells[ncell + tid] = cells[ncell - 1];  // dup pad

    // ---- 3. build combined coefficients into csm (reads zsT-as-A + W) ----
    float bias = 0.0f;
    const int  g   = gbase + tid;
    const bool act = (tid < nst);
    if (act) {
        #pragma unroll
        for (int l = 0; l < LDIM; l++)
            csm[tid * CSTRIDE + l] = W[(size_t)l * G + g] + zsT[tid * LDIM + l];
        bias = bemb[(size_t)b * G + g];
    }
    u64 bias2; PACK2(bias2, bias);
    __syncthreads();                       // csm done; zsT-as-A free for reuse

    // ---- 4. chunk loop over cells (normally one chunk) ----
    for (int cc = 0; cc < ncp; cc += MAXCC) {
        const int nc = min(MAXCC, ncp - cc);          // multiple of GRP
        // stage z transposed: zsT[l*MAXCC + ci] = z[cells[cc+ci]][l]
        for (int i = tid; i < nc * LDIM; i += THREADS) {
            int ci = i & (MAXCC - 1) ? 0 : 0;         // (placeholder, computed below)
            int l  = i / nc;                           // i = l*nc + ci
            ci = i - l * nc;
            zsT[l * MAXCC + ci] = z[(size_t)cells[cc + ci] * LDIM + l];
        }
        for (int i = tid; i < nc; i += THREADS)
            sfs[i] = sf[cells[cc + i]];
        __syncthreads();

        // ---- 5. groups of 16 cells: 8 f32x2 accumulators ----
        for (int jj = 0; jj < nc; jj += GRP) {
            u64 a0 = bias2, a1 = bias2, a2 = bias2, a3 = bias2;
            u64 a4 = bias2, a5 = bias2, a6 = bias2, a7 = bias2;
            #pragma unroll
            for (int l = 0; l < LDIM; l++) {
                float cv = csm[tid * CSTRIDE + l];     // conflict-free LDS.32
                u64 c2; PACK2(c2, cv);
                const ulonglong2* zp =
                    (const ulonglong2*)(zsT + l * MAXCC + jj);  // 16B-aligned
                ulonglong2 p0 = zp[0];                 // cells jj+0..3  (broadcast)
                ulonglong2 p1 = zp[1];                 // cells jj+4..7
                FFMA2(a0, c2, p0.x, a0);
                FFMA2(a1, c2, p0.y, a1);
                FFMA2(a2, c2, p1.x, a2);
                FFMA2(a3, c2, p1.y, a3);
                ulonglong2 p2 = zp[2];                 // cells jj+8..11
                ulonglong2 p3 = zp[3];                 // cells jj+12..15
                FFMA2(a4, c2, p2.x, a4);
                FFMA2(a5, c2, p2.y, a5);
                FFMA2(a6, c2, p3.x, a6);
                FFMA2(a7, c2, p3.y, a7);
            }
            if (act) {
                float v[GRP];
                UNPACK2(v[ 0], v[ 1], a0);
                UNPACK2(v[ 2], v[ 3], a1);
                UNPACK2(v[ 4], v[ 5], a2);
                UNPACK2(v[ 6], v[ 7], a3);
                UNPACK2(v[ 8], v[ 9], a4);
                UNPACK2(v[10], v[11], a5);
                UNPACK2(v[12], v[13], a6);
                UNPACK2(v[14], v[15], a7);
                #pragma unroll
                for (int k = 0; k < GRP; k++) {
                    // duplicate-padded cells store identical values: benign
                    out[(size_t)cells[cc + jj + k] * G + g] =
                        softplus_fast(v[k]) * sfs[jj + k];
                }
            }
        }
        __syncthreads();                   // zsT readers done before restage
    }
}

// ---------------------------------------------------------------------------
// Inputs (metadata order): z, batch_covariate, size_factor, W_amat, A_emb,
//                          b_emb, px_r.  Output: mean [N,G] ++ inv_disp [G].
// ---------------------------------------------------------------------------
extern "C" void kernel_launch(void* const* d_in, const int* in_sizes, int n_in,
                              void* d_out, int out_size) {
    const float* z    = (const float*)d_in[0];
    const int*   bc   = (const int*)  d_in[1];
    const float* sf   = (const float*)d_in[2];
    const float* W    = (const float*)d_in[3];
    const float* A    = (const float*)d_in[4];
    const float* bemb = (const float*)d_in[5];
    const float* px_r = (const float*)d_in[6];
    float* out = (float*)d_out;

    const int N  = in_sizes[1];        // 1024
    const int G  = in_sizes[6];        // 10000
    const int NB = in_sizes[5] / G;    // 64

    dim3 grid((G + GPB - 1) / GPB, NB + 1);
    fused_decoder_kernel<<<grid, THREADS>>>(z, bc, sf, W, A, bemb, px_r, out, N, G, NB);
}

// round 17
// speedup vs baseline: 1.5500x; 1.5500x over previous
#include <cuda_runtime.h>
#include <cuda_bf16.h>
#include <math.h>
#include <stdint.h>

// Problem constants (reference: N=1024, L=30, G=10000, NB=64)
#define LDIM    30
#define ZROW    32           // padded z row (2 zero pads) -> LDS.128 inner loop
#define GPB     128          // genes per tile (= THREADS, 1 gene/thread)
#define THREADS 128
#define XG      40           // block x covers tiles {x, x+40} (NT=79)
#define CHUNK   64           // cells staged per z chunk (ncell~16 -> 1 chunk)
#define NMAX    1024

__device__ __forceinline__ float softplus_fast(float x) {
    // max(x,0) + log1p(exp(-|x|)); fast intrinsics (rel err ~1e-6 << 1e-3 budget)
    return fmaxf(x, 0.0f) + __logf(1.0f + __expf(-fabsf(x)));
}

__device__ __forceinline__ void cp_async16(unsigned int saddr, const void* gptr) {
    asm volatile("cp.async.cg.shared.global [%0], [%1], 16;\n" :: "r"(saddr), "l"(gptr));
}
__device__ __forceinline__ void cp_commit() { asm volatile("cp.async.commit_group;\n" ::: "memory"); }
__device__ __forceinline__ void cp_wait0()  { asm volatile("cp.async.wait_group 0;\n" ::: "memory"); }

// ---------------------------------------------------------------------------
// grid = (XG, NB + 1), block = 128 threads.
//   y <  NB : batch y, gene tiles {x, x+XG}. Single A buffer: abuf is dead
//             after coefficient extraction, so tile t+1's cp.async is issued
//             right after the post-build sync and flies WHILE tile t's
//             mainloop runs -> A latency exposed only once per block.
//   y == NB : inverse_dispersion = exp(px_r)
// ---------------------------------------------------------------------------
__global__ __launch_bounds__(THREADS, 8) void fused_decoder_kernel(
    const float* __restrict__ z,      // [N, L]
    const int*   __restrict__ bc,     // [N]
    const float* __restrict__ sf,     // [N, 1]
    const float* __restrict__ W,      // [L, G]
    const float* __restrict__ A,      // [NB, G, L]
    const float* __restrict__ bemb,   // [NB, G]
    const float* __restrict__ px_r,   // [G]
    float* __restrict__ out,          // [N, G] ++ [G]
    int N, int G, int NB)
{
    // ---- exp(px_r) slice ----
    if (blockIdx.y == (unsigned)NB) {
        float* od = out + (size_t)N * G;
        for (int g = blockIdx.x * THREADS + threadIdx.x; g < G; g += gridDim.x * THREADS)
            od[g] = __expf(px_r[g]);
        return;
    }

    __shared__ float as[GPB * LDIM];        // 15 KB  A tile (cp.async, re-used per tile)
    __shared__ float zs[CHUNK * ZROW];      //  8 KB  z chunk, padded rows
    __shared__ int   cells[NMAX + 2];       //  4 KB  cell list (padded to even)
    __shared__ float sfs[CHUNK];
    __shared__ int   scount;

    const int tid = threadIdx.x;
    const int b   = blockIdx.y;
    const int xg  = blockIdx.x;
    const int NT  = (G + GPB - 1) / GPB;    // 79 tiles

    // prefetch tile t's A into as[] (caller guarantees as[] free)
    auto prefetch_tile = [&](int t) {
        const int nst = min(GPB, G - t * GPB);
        const float4* src4 = (const float4*)(A + ((size_t)b * G + (size_t)t * GPB) * LDIM);
        unsigned int  dst  = (unsigned int)__cvta_generic_to_shared(&as[0]);
        const int w4 = (nst * LDIM) >> 2;   // nst*30 divisible by 4
        for (int i = tid; i < w4; i += THREADS) cp_async16(dst + i * 16, src4 + i);
        cp_commit();
    };

    // ---- kick off first tile's A load (hides behind compaction) ----
    prefetch_tile(xg);

    // ---- compact this batch's cell list once (bc: 4 KB, L2-hot) ----
    if (tid == 0) scount = 0;
    __syncthreads();
    for (int n = tid; n < N; n += THREADS) {
        if (bc[n] == b) {
            int p = atomicAdd(&scount, 1);
            cells[p] = n;
        }
    }
    __syncthreads();
    const int ncell = scount;
    if (ncell == 0) { cp_wait0(); return; }     // uniform across block
    const int ncp = (ncell + 1) & ~1;           // pad to even
    if (tid == 0 && ncp != ncell) cells[ncell] = cells[ncell - 1];

    float c[ZROW];
    c[30] = 0.0f; c[31] = 0.0f;

    for (int cc = 0; cc < ncp; cc += CHUNK) {   // normally a single iteration
        const int nc = min(CHUNK, ncp - cc);
        __syncthreads();                        // prev chunk's zs readers done
        // stage z rows (padded to 32, zero pads) + size factors
        for (int i = tid; i < nc * (LDIM / 2); i += THREADS) {
            int ci = i / (LDIM / 2), l = i - ci * (LDIM / 2);
            float2 v = *(const float2*)(z + (size_t)cells[cc + ci] * LDIM + 2 * l);
            *(float2*)(zs + ci * ZROW + 2 * l) = v;
        }
        for (int i = tid; i < nc; i += THREADS) {
            zs[i * ZROW + 30] = 0.0f;
            zs[i * ZROW + 31] = 0.0f;
            sfs[i] = sf[cells[cc + i]];
        }

        // ---- tile loop: A(t+1) flight overlaps mainloop(t) ----
        for (int t = xg; t < NT; t += XG) {
            cp_wait0();
            __syncthreads();                    // as[] arrived + zs staged visible

            const int  nst = min(GPB, G - t * GPB);
            const int  gt  = t * GPB + tid;
            const bool act = (tid < nst);
            float bias = 0.0f;
            if (act) {
                #pragma unroll
                for (int l = 0; l < LDIM; l++)
                    c[l] = W[(size_t)l * G + gt] + as[tid * LDIM + l];   // W L2-hot
                bias = bemb[(size_t)b * G + gt];
            }
            __syncthreads();                    // everyone done reading as[]

            // next tile's A (or next chunk's re-load of tile xg) into as[]
            if (t + XG < NT)           prefetch_tile(t + XG);
            else if (cc + CHUNK < ncp) prefetch_tile(xg);

            if (act) {
                for (int j = 0; j < nc; j += 2) {
                    const float4* z0 = (const float4*)(zs + (j    ) * ZROW);
                    const float4* z1 = (const float4*)(zs + (j + 1) * ZROW);
                    float a0 = bias, a1 = bias;
                    #pragma unroll
                    for (int q = 0; q < ZROW / 4; q++) {
                        float4 v0 = z0[q], v1 = z1[q];     // broadcast LDS.128
                        a0 = fmaf(c[4*q+0], v0.x, a0);  a1 = fmaf(c[4*q+0], v1.x, a1);
                        a0 = fmaf(c[4*q+1], v0.y, a0);  a1 = fmaf(c[4*q+1], v1.y, a1);
                        a0 = fmaf(c[4*q+2], v0.z, a0);  a1 = fmaf(c[4*q+2], v1.z, a1);
                        a0 = fmaf(c[4*q+3], v0.w, a0);  a1 = fmaf(c[4*q+3], v1.w, a1);
                    }
                    // duplicate-padded cell stores identical value twice: benign
                    out[(size_t)cells[cc + j    ] * G + gt] = softplus_fast(a0) * sfs[j    ];
                    out[(size_t)cells[cc + j + 1] * G + gt] = softplus_fast(a1) * sfs[j + 1];
                }
            }
        }
    }
}

// ---------------------------------------------------------------------------
// Inputs (metadata order): z, batch_covariate, size_factor, W_amat, A_emb,
//                          b_emb, px_r.  Output: mean [N,G] ++ inv_disp [G].
// ---------------------------------------------------------------------------
extern "C" void kernel_launch(void* const* d_in, const int* in_sizes, int n_in,
                              void* d_out, int out_size) {
    const float* z    = (const float*)d_in[0];
    const int*   bc   = (const int*)  d_in[1];
    const float* sf   = (const float*)d_in[2];
    const float* W    = (const float*)d_in[3];
    const float* A    = (const float*)d_in[4];
    const float* bemb = (const float*)d_in[5];
    const float* px_r = (const float*)d_in[6];
    float* out = (float*)d_out;

    const int N  = in_sizes[1];        // 1024
    const int G  = in_sizes[6];        // 10000
    const int NB = in_sizes[5] / G;    // 64

    dim3 grid(XG, NB + 1);
    fused_decoder_kernel<<<grid, THREADS>>>(z, bc, sf, W, A, bemb, px_r, out, N, G, NB);
}